// round 1
// baseline (speedup 1.0000x reference)
#include <cuda_runtime.h>
#include <math_constants.h>

// Problem constants (shapes fixed by setup_inputs: N=8192, K=16)
#define NMAX   8192
#define KTOP   16
#define SLICES 8
#define SLEN   (NMAX / SLICES)   // 1024 candidates per slice
#define QPB    256               // queries per KNN block
#define RBLK   256               // threads per reduce block

// Scratch: __device__ globals (no allocation allowed)
__device__ float2 g_ch2m[NMAX];
__device__ float  g_sd[SLICES][NMAX][KTOP];   // per-slice top-16 distances
__device__ int    g_si[SLICES][NMAX][KTOP];   // per-slice top-16 indices
__device__ int    g_idx[NMAX * KTOP];         // merged global top-16 indices
__device__ float  g_part[64];                 // per-block partial sums

// ---------------------------------------------------------------------------
// Kernel 1: ch2m[i] = polynomial(ch2[i]; M1, M2)
// y1 = M1[0][0] + M1[0][1]*x2 + M1[1][0]*x1 + M1[1][1]*x1*x2 ; same for y2/M2
// ---------------------------------------------------------------------------
__global__ void poly_kernel(const float* __restrict__ ch2,
                            const float* __restrict__ M1,
                            const float* __restrict__ M2,
                            int N)
{
    int i = blockIdx.x * blockDim.x + threadIdx.x;
    if (i >= N) return;
    float x1 = ch2[2 * i + 0];
    float x2 = ch2[2 * i + 1];
    float y1 = M1[0] + M1[1] * x2 + M1[2] * x1 + M1[3] * (x1 * x2);
    float y2 = M2[0] + M2[1] * x2 + M2[2] * x1 + M2[3] * (x1 * x2);
    g_ch2m[i] = make_float2(y1, y2);
}

// ---------------------------------------------------------------------------
// Kernel 2: sliced brute-force KNN.
// blockIdx.y = slice s; block loads slice into SMEM; each thread owns one
// query and maintains a register-resident sorted top-16 (ascending distance,
// stable w.r.t. candidate index — matches lax.top_k tie behavior).
// ---------------------------------------------------------------------------
__global__ __launch_bounds__(QPB)
void knn_kernel(const float* __restrict__ ch1, int N)
{
    __shared__ float2 cand[SLEN];

    const int s    = blockIdx.y;
    const int sl   = N / SLICES;           // 1024 for N=8192
    const int base = s * sl;

    for (int t = threadIdx.x; t < sl; t += blockDim.x)
        cand[t] = g_ch2m[base + t];
    __syncthreads();

    const int j = blockIdx.x * blockDim.x + threadIdx.x;
    if (j >= N) return;

    const float x1 = ch1[2 * j + 0];
    const float x2 = ch1[2 * j + 1];

    float d[KTOP];
    int   id[KTOP];
#pragma unroll
    for (int m = 0; m < KTOP; ++m) { d[m] = CUDART_INF_F; id[m] = 0x7fffffff; }

#pragma unroll 4
    for (int t = 0; t < sl; ++t) {
        float2 c    = cand[t];
        float  dy1  = __fadd_rn(x1, -c.x);
        float  dy2  = __fadd_rn(x2, -c.y);
        float  dist = __fadd_rn(__fmul_rn(dy1, dy1), __fmul_rn(dy2, dy2));
        if (dist < d[KTOP - 1]) {               // rare path (~6% of iters)
            const int cn = base + t;
#pragma unroll
            for (int m = KTOP - 1; m >= 1; --m) {
                float a = d[m - 1];
                if (dist < a)            { d[m] = a;    id[m] = id[m - 1]; }
                else if (dist < d[m])    { d[m] = dist; id[m] = cn;        }
            }
            if (dist < d[0])             { d[0] = dist; id[0] = cn;        }
        }
    }

#pragma unroll
    for (int m = 0; m < KTOP; ++m) {
        g_sd[s][j][m] = d[m];
        g_si[s][j][m] = id[m];
    }
}

// ---------------------------------------------------------------------------
// Kernel 3: stable 8-way merge of per-slice sorted lists -> global top-16.
// Strict '<' with ascending slice scan preserves (value, index) stability:
// lower slice == lower candidate-index range wins ties.
// ---------------------------------------------------------------------------
__global__ void merge_kernel(int N)
{
    int j = blockIdx.x * blockDim.x + threadIdx.x;
    if (j >= N) return;

    int   ptr[SLICES];
    float head[SLICES];
#pragma unroll
    for (int s = 0; s < SLICES; ++s) { ptr[s] = 0; head[s] = g_sd[s][j][0]; }

    for (int k = 0; k < KTOP; ++k) {
        float best = head[0];
        int   bs   = 0;
#pragma unroll
        for (int s = 1; s < SLICES; ++s)
            if (head[s] < best) { best = head[s]; bs = s; }
        g_idx[j * KTOP + k] = g_si[bs][j][ptr[bs]];
        ptr[bs]++;
        head[bs] = (ptr[bs] < KTOP) ? g_sd[bs][j][ptr[bs]] : CUDART_INF_F;
    }
}

// ---------------------------------------------------------------------------
// Kernel 4: scrambled gather + KL sum + per-block reduction.
// Reference: m = k*N + n ; a = idx[m/K][m%K] ; b = m % N (== n here) ;
// D = 0.5 * (dy1^2/2.25 + dy2^2/2.25) ; expD[n] = sum_k exp(-D) / N ;
// contribution = (expD != 0) ? log(expD) : 0
// ---------------------------------------------------------------------------
__global__ __launch_bounds__(RBLK)
void reduce_kernel(const float* __restrict__ ch1, int N)
{
    const float inv_s4 = 1.0f / 2.25f;   // 1/sigma2^2 ; sigma2 = 1.5 (exact)

    int n = blockIdx.x * blockDim.x + threadIdx.x;
    float v = 0.0f;
    if (n < N) {
        const float x1 = ch1[2 * n + 0];
        const float x2 = ch1[2 * n + 1];
        float ssum = 0.0f;
#pragma unroll
        for (int k = 0; k < KTOP; ++k) {
            int m  = k * N + n;            // < 131072, fits int
            int ar = m / KTOP;
            int ac = m - ar * KTOP;
            int i  = g_idx[ar * KTOP + ac];
            float2 c = g_ch2m[i];
            float dy1 = __fadd_rn(x1, -c.x);
            float dy2 = __fadd_rn(x2, -c.y);
            float D = 0.5f * __fadd_rn(__fmul_rn(dy1, dy1) * inv_s4,
                                       __fmul_rn(dy2, dy2) * inv_s4);
            ssum += expf(-D);
        }
        float expD = ssum / (float)N;
        if (expD != 0.0f) v = logf(expD);
    }

    // block reduction (shared), deterministic within fixed block shape
    __shared__ float red[RBLK];
    red[threadIdx.x] = v;
    __syncthreads();
#pragma unroll
    for (int off = RBLK / 2; off > 0; off >>= 1) {
        if (threadIdx.x < off) red[threadIdx.x] += red[threadIdx.x + off];
        __syncthreads();
    }
    if (threadIdx.x == 0) g_part[blockIdx.x] = red[0];
}

// ---------------------------------------------------------------------------
// Kernel 5: deterministic final sum of partials, negate, write d_out[0].
// ---------------------------------------------------------------------------
__global__ void final_kernel(float* __restrict__ out, int nparts)
{
    if (threadIdx.x == 0 && blockIdx.x == 0) {
        float s = 0.0f;
        for (int i = 0; i < nparts; ++i) s += g_part[i];
        out[0] = -s;
    }
}

// ---------------------------------------------------------------------------
extern "C" void kernel_launch(void* const* d_in, const int* in_sizes, int n_in,
                              void* d_out, int out_size)
{
    const float* ch1 = (const float*)d_in[0];
    const float* ch2 = (const float*)d_in[1];
    const float* M1  = (const float*)d_in[2];
    const float* M2  = (const float*)d_in[3];
    float* out = (float*)d_out;

    const int N = in_sizes[0] / 2;       // 8192

    // 1) polynomial map
    poly_kernel<<<(N + 255) / 256, 256>>>(ch2, M1, M2, N);

    // 2) sliced KNN: grid (N/QPB, SLICES)
    dim3 kgrid(N / QPB, SLICES);
    knn_kernel<<<kgrid, QPB>>>(ch1, N);

    // 3) merge slices
    merge_kernel<<<(N + 255) / 256, 256>>>(N);

    // 4) gather + partial reduce
    const int rblocks = (N + RBLK - 1) / RBLK;   // 32
    reduce_kernel<<<rblocks, RBLK>>>(ch1, N);

    // 5) final deterministic sum
    final_kernel<<<1, 32>>>(out, rblocks);
}

// round 2
// speedup vs baseline: 2.1203x; 2.1203x over previous
#include <cuda_runtime.h>
#include <math_constants.h>

// Problem constants (shapes fixed by setup_inputs: N=8192, K=16)
#define NMAX   8192
#define KTOP   16
#define SLICES 8
#define SLEN   (NMAX / SLICES)   // 1024 candidates per slice
#define QPB    128               // queries per KNN block
#define CHUNK  32                // candidates per branch-free scan chunk
#define MPB    64                // threads per merge block

// Scratch: __device__ globals (no allocation allowed)
__device__ float2 g_ch2m[NMAX];
__device__ float  g_sd[SLICES][KTOP][NMAX];   // per-slice top-16 dists, transposed
__device__ int    g_si[SLICES][KTOP][NMAX];   // per-slice top-16 indices
__device__ int    g_idx[NMAX * KTOP];         // merged global top-16 (query-major)
__device__ float  g_part[512];                // per-block partial sums

// ---------------------------------------------------------------------------
// Kernel 1: ch2m[i] = polynomial(ch2[i]; M1, M2)
// ---------------------------------------------------------------------------
__global__ void poly_kernel(const float* __restrict__ ch2,
                            const float* __restrict__ M1,
                            const float* __restrict__ M2,
                            int N)
{
    int i = blockIdx.x * blockDim.x + threadIdx.x;
    if (i >= N) return;
    float x1 = ch2[2 * i + 0];
    float x2 = ch2[2 * i + 1];
    float y1 = M1[0] + M1[1] * x2 + M1[2] * x1 + M1[3] * (x1 * x2);
    float y2 = M2[0] + M2[1] * x2 + M2[2] * x1 + M2[3] * (x1 * x2);
    g_ch2m[i] = make_float2(y1, y2);
}

// ---------------------------------------------------------------------------
// Sorted top-16 insert, fully predicated (no guard needed: a non-qualifying
// dist leaves the list unchanged). Strict '<' => stable ties (earlier index
// wins), matching lax.top_k.
// ---------------------------------------------------------------------------
__device__ __forceinline__ void insert16(float (&d)[KTOP], int (&id)[KTOP],
                                         float dist, int cn)
{
#pragma unroll
    for (int m = KTOP - 1; m >= 1; --m) {
        bool up   = dist < d[m - 1];
        bool here = (!up) && (dist < d[m]);
        float nd  = up ? d[m - 1]  : (here ? dist : d[m]);
        int   ni  = up ? id[m - 1] : (here ? cn   : id[m]);
        d[m] = nd; id[m] = ni;
    }
    if (dist < d[0]) { d[0] = dist; id[0] = cn; }
}

// ---------------------------------------------------------------------------
// Kernel 2: sliced brute-force KNN with chunked branch-free filtering.
// Scan loop per candidate: LDS + 4 FP + FSETP + 2 unconditional STS + bp bump.
// Drain loop (divergent, rare) does the expensive sorted insert.
// ---------------------------------------------------------------------------
__global__ __launch_bounds__(QPB)
void knn_kernel(const float* __restrict__ ch1, int N)
{
    __shared__ __align__(16) float2 cand[SLEN];        // 8 KB
    __shared__ float buf_d[CHUNK + 1][QPB];            // 16.9 KB
    __shared__ int   buf_i[CHUNK + 1][QPB];            // 16.9 KB

    const int s    = blockIdx.y;
    const int base = s * SLEN;
    const int tid  = threadIdx.x;

    for (int t = tid; t < SLEN; t += QPB)
        cand[t] = g_ch2m[base + t];
    __syncthreads();

    const int j = blockIdx.x * QPB + tid;
    const float x1 = ch1[2 * j + 0];
    const float x2 = ch1[2 * j + 1];

    float d[KTOP];
    int   id[KTOP];
#pragma unroll
    for (int m = 0; m < KTOP; ++m) { d[m] = CUDART_INF_F; id[m] = 0x7fffffff; }

    float T = CUDART_INF_F;

    for (int cb = 0; cb < SLEN; cb += CHUNK) {
        int bp = 0;
        // branch-free scan: unconditional store, conditional pointer bump
#pragma unroll
        for (int u = 0; u < CHUNK; u += 2) {
            float4 cc = *reinterpret_cast<const float4*>(&cand[cb + u]);

            float dy1a = x1 - cc.x;
            float dy2a = x2 - cc.y;
            float da   = fmaf(dy2a, dy2a, dy1a * dy1a);
            buf_d[bp][tid] = da;
            buf_i[bp][tid] = cb + u;
            bp += (da < T) ? 1 : 0;

            float dy1b = x1 - cc.z;
            float dy2b = x2 - cc.w;
            float db   = fmaf(dy2b, dy2b, dy1b * dy1b);
            buf_d[bp][tid] = db;
            buf_i[bp][tid] = cb + u + 1;
            bp += (db < T) ? 1 : 0;
        }
        // drain (forward order preserves tie stability)
        for (int i2 = 0; i2 < bp; ++i2)
            insert16(d, id, buf_d[i2][tid], base + buf_i[i2][tid]);
        T = d[KTOP - 1];
    }

#pragma unroll
    for (int m = 0; m < KTOP; ++m) {
        g_sd[s][m][j] = d[m];      // coalesced (adjacent j contiguous)
        g_si[s][m][j] = id[m];
    }
}

// ---------------------------------------------------------------------------
// Kernel 3: stable 8-way merge, register-resident state, SMEM-staged dists.
// Strict '<' with ascending slice order preserves index-order tie breaking.
// ---------------------------------------------------------------------------
__global__ __launch_bounds__(MPB)
void merge_kernel(int N)
{
    __shared__ float stage[SLICES][KTOP][MPB];   // 32 KB

    const int tid = threadIdx.x;
    const int j   = blockIdx.x * MPB + tid;
    if (j >= N) return;

    // stage this thread's 128 distances (own column only -> no sync needed)
#pragma unroll
    for (int s = 0; s < SLICES; ++s)
#pragma unroll
        for (int m = 0; m < KTOP; ++m)
            stage[s][m][tid] = g_sd[s][m][j];

    float head[SLICES];
    int   ptr[SLICES];
#pragma unroll
    for (int s = 0; s < SLICES; ++s) { ptr[s] = 0; head[s] = stage[s][0][tid]; }

    int pickS[KTOP], pickP[KTOP];
#pragma unroll
    for (int k = 0; k < KTOP; ++k) {
        float best = head[0];
        int   bs   = 0;
#pragma unroll
        for (int s = 1; s < SLICES; ++s)
            if (head[s] < best) { best = head[s]; bs = s; }
        pickS[k] = bs;
#pragma unroll
        for (int s = 0; s < SLICES; ++s) {
            if (bs == s) {
                pickP[k] = ptr[s];
                int p = ptr[s] + 1;
                ptr[s] = p;
                head[s] = (p < KTOP) ? stage[s][p][tid] : CUDART_INF_F;
            }
        }
    }

    // gather winner indices with full MLP, then write
    const int* sib = &g_si[0][0][0];
    int ids[KTOP];
#pragma unroll
    for (int k = 0; k < KTOP; ++k)
        ids[k] = sib[(pickS[k] * KTOP + pickP[k]) * NMAX + j];
#pragma unroll
    for (int k = 0; k < KTOP; ++k)
        g_idx[j * KTOP + k] = ids[k];
}

// ---------------------------------------------------------------------------
// Kernel 4: one thread per (query, k). Reference's scrambled gather
// idx[m/K][m%K] with m = k*N + n flattens to g_idx[k*N + n] exactly
// (since K | N). Shuffle-reduce over the 16 k-lanes, log, block partial.
// ---------------------------------------------------------------------------
__global__ __launch_bounds__(256)
void reduce_kernel(const float* __restrict__ ch1, int N)
{
    const float scale = -0.5f / 2.25f;   // -0.5 / sigma2^2, sigma2 = 1.5
    const int t = threadIdx.x;
    const int q = blockIdx.x * 16 + (t >> 4);
    const int k = t & 15;

    int a = g_idx[k * N + q];            // coalesced along q
    float2 c = g_ch2m[a];
    float x1 = ch1[2 * q + 0];
    float x2 = ch1[2 * q + 1];
    float dy1 = x1 - c.x;
    float dy2 = x2 - c.y;
    float e = expf(scale * fmaf(dy2, dy2, dy1 * dy1));

    // reduce over the 16 k-lanes (xor keeps 16-groups intact)
#pragma unroll
    for (int o = 8; o > 0; o >>= 1)
        e += __shfl_xor_sync(0xffffffffu, e, o);

    __shared__ float sq[16];
    if (k == 0) {
        float expD = e * (1.0f / (float)NMAX);
        sq[t >> 4] = (expD != 0.0f) ? logf(expD) : 0.0f;
    }
    __syncthreads();

    if (t < 16) {
        float x = sq[t];
#pragma unroll
        for (int o = 8; o > 0; o >>= 1)
            x += __shfl_xor_sync(0x0000ffffu, x, o, 16);
        if (t == 0) g_part[blockIdx.x] = x;
    }
}

// ---------------------------------------------------------------------------
// Kernel 5: deterministic tree-sum of 512 partials, negate, write out.
// ---------------------------------------------------------------------------
__global__ __launch_bounds__(512)
void final_kernel(float* __restrict__ out)
{
    __shared__ float red[512];
    red[threadIdx.x] = g_part[threadIdx.x];
    __syncthreads();
#pragma unroll
    for (int off = 256; off > 0; off >>= 1) {
        if (threadIdx.x < off) red[threadIdx.x] += red[threadIdx.x + off];
        __syncthreads();
    }
    if (threadIdx.x == 0) out[0] = -red[0];
}

// ---------------------------------------------------------------------------
extern "C" void kernel_launch(void* const* d_in, const int* in_sizes, int n_in,
                              void* d_out, int out_size)
{
    const float* ch1 = (const float*)d_in[0];
    const float* ch2 = (const float*)d_in[1];
    const float* M1  = (const float*)d_in[2];
    const float* M2  = (const float*)d_in[3];
    float* out = (float*)d_out;

    const int N = in_sizes[0] / 2;       // 8192

    poly_kernel<<<(N + 255) / 256, 256>>>(ch2, M1, M2, N);

    dim3 kgrid(N / QPB, SLICES);         // (64, 8)
    knn_kernel<<<kgrid, QPB>>>(ch1, N);

    merge_kernel<<<N / MPB, MPB>>>(N);   // 128 blocks x 64

    reduce_kernel<<<N / 16, 256>>>(ch1, N);  // 512 blocks: 16 q x 16 k each

    final_kernel<<<1, 512>>>(out);
}